// round 14
// baseline (speedup 1.0000x reference)
#include <cuda_runtime.h>
#include <math.h>

#define NJ 17
#define NP 14
#define NC 59          // 17 joint channels + 14*3 pair channels
#define NG 9           // groups per batch: 2 joint groups + 7 two-pair groups

__constant__ int c_pj[NP] = {0,1,2,0,4,5,0,8,14,15,8,11,12,8};
__constant__ int c_cj[NP] = {1,2,3,4,5,6,8,14,15,16,11,12,13,10};

// One double partial per block (B*NG blocks), plus completion counter.
__device__ double g_part[256 * NG];
__device__ int    g_cnt;          // zero-initialized; self-resets each launch

__device__ __forceinline__ float warp_red_f(float v) {
#pragma unroll
    for (int o = 16; o > 0; o >>= 1) v += __shfl_down_sync(0xffffffffu, v, o);
    return v;
}

__device__ __forceinline__ float row_acc2(float4 m, float gA, float gB,
                                          float4 eA, float4 eB) {
    const float d0 = m.x - (gA * eA.x + gB * eB.x);
    const float d1 = m.y - (gA * eA.y + gB * eB.y);
    const float d2 = m.z - (gA * eA.z + gB * eB.z);
    const float d3 = m.w - (gA * eA.w + gB * eB.w);
    return d0 * d0 + d1 * d1 + d2 * d2 + d3 * d3;
}

__device__ __forceinline__ float row_acc1(float4 m, float gA, float4 eA) {
    const float d0 = m.x - gA * eA.x;
    const float d1 = m.y - gA * eA.y;
    const float d2 = m.z - gA * eA.z;
    const float d3 = m.w - gA * eA.w;
    return d0 * d0 + d1 * d1 + d2 * d2 + d3 * d3;
}

// Grid (B, 9). Block (b,g):
//   g=0: joint channels 0..8   (9 ch, single L2D accumulator)
//   g=1: joint channels 9..16  (8 ch, single L2D accumulator) + l3d
//   g=2..8: pairs 2(g-2), 2(g-2)+1  (6 channels, per-channel sums for sqrt)
// Channels of a group are contiguous in middle_out. Prologue builds only the
// Gaussian vectors this group needs (hardware __expf). Channel loop streams
// 2 channels per iteration (8 float4 in flight). One double partial per block;
// last-arriving block reduces all B*NG partials.
__global__ __launch_bounds__(256) void mpjpe_fused_kernel(
    const float* __restrict__ pred,
    const float* __restrict__ joints,
    const float* __restrict__ middle_out,
    const float* __restrict__ joint2d,
    float* __restrict__ out, int B)
{
    const int b = blockIdx.x;
    const int g = blockIdx.y;
    const int t = threadIdx.x;
    const int w = t >> 5;

    int c0, nch;
    if (g == 0)      { c0 = 0;              nch = 9; }
    else if (g == 1) { c0 = 9;              nch = 8; }
    else             { c0 = 17 + 6*(g - 2); nch = 6; }

    __shared__ __align__(16) float heat[18 * 64];  // vector v at heat[v*64]
    __shared__ float wsum[8][8];
    __shared__ float chan[8];
    __shared__ float l3s[51];
    __shared__ int   s_win;
    __shared__ double smd[8];
    if (t == 0) s_win = 0;

    // Build only the vectors this group needs.
    // Vector v: slot s = v>>1, axis = v&1.
    //   joint groups: slot s -> joint c0 + s
    //   pair groups:  slot s -> s=2*pl+pc, pl=pair_local, pc=0 parent/1 child
    const int nvec = (g == 0) ? 18 : (g == 1) ? 16 : 8;
    for (int idx = t; idx < nvec * 64; idx += 256) {
        const int v = idx >> 6, lane = idx & 63;
        int j;
        if (g < 2) {
            j = c0 + (v >> 1);
        } else {
            const int p = 2 * (g - 2) + (v >> 2);
            j = ((v >> 1) & 1) ? c_cj[p] : c_pj[p];
        }
        const float x  = joint2d[(b * NJ + j) * 2 + (v & 1)] * 64.f;
        const float rx = fminf(fmaxf(rintf(x), 0.f), 63.f);
        const float mind = (rx - x) * (rx - x);      // min over grid of (i-x)^2
        const float dd = (float)lane - x;
        heat[idx] = __expf((mind - dd * dd) * 0.25f); // exact max-normalization
    }
    if (g == 1 && t < 51)
        l3s[t] = fabsf(joints[b * 51 + t] - pred[b * 51 + t]);
    __syncthreads();

    const float4* mobase =
        reinterpret_cast<const float4*>(middle_out) + ((size_t)b * NC + c0) * 1024;
    const int h0 = t >> 4;          // rows h0, h0+16, +32, +48
    const int w4 = t & 15;

    if (g < 2) {
        // ---- joint channels: GT = ex[h]*ey[w], single accumulator ----
        float acc = 0.f;
#pragma unroll
        for (int i = 0; i < 8; i += 2) {
            const float4 a0 = __ldcs(&mobase[i * 1024 + t]);
            const float4 a1 = __ldcs(&mobase[i * 1024 + t + 256]);
            const float4 a2 = __ldcs(&mobase[i * 1024 + t + 512]);
            const float4 a3 = __ldcs(&mobase[i * 1024 + t + 768]);
            const float4 b0 = __ldcs(&mobase[(i+1) * 1024 + t]);
            const float4 b1 = __ldcs(&mobase[(i+1) * 1024 + t + 256]);
            const float4 b2 = __ldcs(&mobase[(i+1) * 1024 + t + 512]);
            const float4 b3 = __ldcs(&mobase[(i+1) * 1024 + t + 768]);

            const float* exa = &heat[(2*i    ) * 64];
            const float4 eya = reinterpret_cast<const float4*>(&heat[(2*i+1)*64])[w4];
            const float* exb = &heat[(2*i + 2) * 64];
            const float4 eyb = reinterpret_cast<const float4*>(&heat[(2*i+3)*64])[w4];

            acc += row_acc1(a0, exa[h0     ], eya);
            acc += row_acc1(a1, exa[h0 + 16], eya);
            acc += row_acc1(a2, exa[h0 + 32], eya);
            acc += row_acc1(a3, exa[h0 + 48], eya);
            acc += row_acc1(b0, exb[h0     ], eyb);
            acc += row_acc1(b1, exb[h0 + 16], eyb);
            acc += row_acc1(b2, exb[h0 + 32], eyb);
            acc += row_acc1(b3, exb[h0 + 48], eyb);
        }
        if (nch == 9) {             // g==0 tail channel
            const int i = 8;
            const float4 a0 = __ldcs(&mobase[i * 1024 + t]);
            const float4 a1 = __ldcs(&mobase[i * 1024 + t + 256]);
            const float4 a2 = __ldcs(&mobase[i * 1024 + t + 512]);
            const float4 a3 = __ldcs(&mobase[i * 1024 + t + 768]);
            const float* exa = &heat[(2*i) * 64];
            const float4 eya = reinterpret_cast<const float4*>(&heat[(2*i+1)*64])[w4];
            acc += row_acc1(a0, exa[h0     ], eya);
            acc += row_acc1(a1, exa[h0 + 16], eya);
            acc += row_acc1(a2, exa[h0 + 32], eya);
            acc += row_acc1(a3, exa[h0 + 48], eya);
        }
        acc = warp_red_f(acc);
        if ((t & 31) == 0) wsum[w][0] = acc;
        __syncthreads();

        if (t == 0) {
            float l2 = 0.f;
#pragma unroll
            for (int ww = 0; ww < 8; ww++) l2 += wsum[ww][0];
            double part = 0.005 * (double)l2;
            if (g == 1) {
                float l3 = 0.f;
#pragma unroll
                for (int i = 0; i < 51; i++) l3 += l3s[i];
                part += (double)l3;
            }
            g_part[b * NG + g] = part;
            __threadfence();
            const int old = atomicAdd(&g_cnt, 1);
            if (old == NG * B - 1) s_win = 1;
        }
    } else {
        // ---- two pairs, 6 channels: per-channel sums (needed for sqrt) ----
        const int p0 = 2 * (g - 2);
        const float dz0 = joints[(b*NJ + c_pj[p0  ])*3 + 2] - joints[(b*NJ + c_cj[p0  ])*3 + 2];
        const float dz1 = joints[(b*NJ + c_pj[p0+1])*3 + 2] - joints[(b*NJ + c_cj[p0+1])*3 + 2];
        const int r0 = (dz0 > 0.1f) ? 1 : ((fabsf(dz0) < 0.1f) ? 0 : -1);
        const int r1 = (dz1 > 0.1f) ? 1 : ((fabsf(dz1) < 0.1f) ? 0 : -1);

#pragma unroll
        for (int i = 0; i < 6; i += 2) {
            const float4 a0 = __ldcs(&mobase[i * 1024 + t]);
            const float4 a1 = __ldcs(&mobase[i * 1024 + t + 256]);
            const float4 a2 = __ldcs(&mobase[i * 1024 + t + 512]);
            const float4 a3 = __ldcs(&mobase[i * 1024 + t + 768]);
            const float4 b0 = __ldcs(&mobase[(i+1) * 1024 + t]);
            const float4 b1 = __ldcs(&mobase[(i+1) * 1024 + t + 256]);
            const float4 b2 = __ldcs(&mobase[(i+1) * 1024 + t + 512]);
            const float4 b3 = __ldcs(&mobase[(i+1) * 1024 + t + 768]);

#pragma unroll
            for (int u = 0; u < 2; u++) {
                const int ii = i + u;             // compile-time after unroll
                const int pl = (ii >= 3) ? 1 : 0;
                const int ch = ii - 3 * pl;
                const int r  = pl ? r1 : r0;
                const float ca = (ch == 1) ? 1.f : 0.f;
                const float cb = ((ch == 0 && r == -1) ||
                                  (ch == 1 && r ==  0) ||
                                  (ch == 2 && r ==  1)) ? 1.f : 0.f;
                const int sp = 2 * pl, sc = sp + 1;
                const float* exP = &heat[(2*sp    ) * 64];
                const float* exC = &heat[(2*sc    ) * 64];
                const float4 eyP = reinterpret_cast<const float4*>(&heat[(2*sp+1)*64])[w4];
                const float4 eyC = reinterpret_cast<const float4*>(&heat[(2*sc+1)*64])[w4];

                const float4 m0 = u ? b0 : a0;
                const float4 m1 = u ? b1 : a1;
                const float4 m2 = u ? b2 : a2;
                const float4 m3 = u ? b3 : a3;

                float acc = 0.f;
                acc += row_acc2(m0, ca*exP[h0     ], cb*exC[h0     ], eyP, eyC);
                acc += row_acc2(m1, ca*exP[h0 + 16], cb*exC[h0 + 16], eyP, eyC);
                acc += row_acc2(m2, ca*exP[h0 + 32], cb*exC[h0 + 32], eyP, eyC);
                acc += row_acc2(m3, ca*exP[h0 + 48], cb*exC[h0 + 48], eyP, eyC);

                acc = warp_red_f(acc);
                if ((t & 31) == 0) wsum[w][ii] = acc;
            }
        }
        __syncthreads();

        if (t < 6) {
            float s = 0.f;
#pragma unroll
            for (int ww = 0; ww < 8; ww++) s += wsum[ww][t];
            chan[t] = s;
        }
        __syncthreads();

        if (t == 0) {
            const float n0 = sqrtf(chan[0]) + sqrtf(chan[1]) + sqrtf(chan[2]);
            const float n1 = sqrtf(chan[3]) + sqrtf(chan[4]) + sqrtf(chan[5]);
            g_part[b * NG + g] = 0.005 * (double)(n0 * n0 + n1 * n1);
            __threadfence();
            const int old = atomicAdd(&g_cnt, 1);
            if (old == NG * B - 1) s_win = 1;
        }
    }
    __syncthreads();

    if (s_win) {
        __threadfence();                       // acquire published partials
        double db = 0.0;
        for (int idx = t; idx < NG * B; idx += 256) db += __ldcg(&g_part[idx]);
#pragma unroll
        for (int o = 16; o > 0; o >>= 1) db += __shfl_down_sync(0xffffffffu, db, o);
        if ((t & 31) == 0) smd[t >> 5] = db;
        __syncthreads();
        if (t == 0) {
            double sum = 0.0;
            for (int ww = 0; ww < 8; ww++) sum += smd[ww];
            out[0] = (float)(sum / (double)B);
            g_cnt = 0;                         // reset for next graph replay
        }
    }
}

extern "C" void kernel_launch(void* const* d_in, const int* in_sizes, int n_in,
                              void* d_out, int out_size)
{
    const float* pred   = (const float*)d_in[0];
    const float* joints = (const float*)d_in[1];
    const float* mo     = (const float*)d_in[2];
    const float* j2d    = (const float*)d_in[3];

    int B = in_sizes[0] / (NJ * 3);
    if (B > 256) B = 256;   // scratch capacity guard (problem uses B=256)

    dim3 grid(B, NG);
    mpjpe_fused_kernel<<<grid, 256>>>(pred, joints, mo, j2d, (float*)d_out, B);
}